// round 17
// baseline (speedup 1.0000x reference)
#include <cuda_runtime.h>
#include <cuda_fp16.h>
#include <cstdint>

#define RES    300
#define NCOMP  48
#define PCH    64                           // padded channel stride (128B rows)
#define NFEAT  27
#define KTOT   144
#define NPTS_BLK 192
#define THREADS  384

#define FROWB  304
#define F_OFF    0
#define F_BYTES  (NPTS_BLK * FROWB)         // 58368
#define WH_OFF   F_BYTES
#define WHROWB 336
#define WH_BYTES (32 * WHROWB)              // 10752
#define XYZ_OFF  (WH_OFF + WH_BYTES)        // 69120
#define XYZ_BYTES (NPTS_BLK * 3 * 4)        // 2304
#define SMEM_DYN (XYZ_OFF + XYZ_BYTES)      // 71424 -> 3 CTAs/SM

// Scratch: channel-last transposed fp16 copies, 64-ch padded rows.
__device__ __align__(128) __half g_planesH[3u * RES * RES * PCH];
__device__ __align__(128) __half g_linesH [3u * RES * PCH];

// ---------------------------------------------------------------------------
// Transpose planes: read fp32 coalesced into smem tile, write packed uint4
// (8 fp16 channels) per store -> full-width global stores.
// ---------------------------------------------------------------------------
__global__ void transpose_planes_kernel(const float* __restrict__ planes) {
    __shared__ float tile[NCOMP][33];
    const int i  = blockIdx.z;
    const int y  = blockIdx.y;
    const int xt = blockIdx.x * 32;
    const int t  = threadIdx.x;
    const int tx = t & 31;
    const int tc = t >> 5;
    const int x  = xt + tx;
    #pragma unroll
    for (int r = 0; r < 6; r++) {
        const int c = tc + 8 * r;
        if (x < RES)
            tile[c][tx] = planes[(((size_t)i * NCOMP + c) * RES + y) * RES + x];
    }
    __syncthreads();
    const int nx = min(32, RES - xt);
    __half* outb = g_planesH + (((size_t)i * RES + y) * RES + xt) * PCH;
    for (int e = t; e < nx * 6; e += 256) {       // 6 groups of 8 channels per x
        const int xl  = e / 6;
        const int grp = e - xl * 6;
        const int c0  = grp * 8;
        uint32_t w[4];
        #pragma unroll
        for (int q = 0; q < 4; q++) {
            __half2 h = __floats2half2_rn(tile[c0 + 2*q][xl], tile[c0 + 2*q + 1][xl]);
            w[q] = *reinterpret_cast<const uint32_t*>(&h);
        }
        *reinterpret_cast<uint4*>(outb + (size_t)xl * PCH + c0) =
            make_uint4(w[0], w[1], w[2], w[3]);
    }
}

__global__ void transpose_lines_kernel(const float* __restrict__ lines) {
    const int e = blockIdx.x * 256 + threadIdx.x;
    if (e >= 3 * RES * NCOMP) return;
    const int c  = e % NCOMP;
    const int ir = e / NCOMP;
    const int r  = ir % RES;
    const int i  = ir / RES;
    g_linesH[(size_t)ir * PCH + c] = __float2half(lines[((size_t)i * NCOMP + c) * RES + r]);
}

// ---------------------------------------------------------------------------
__device__ __forceinline__ uint32_t smem_u32(const void* p) {
    uint32_t a;
    asm("{ .reg .u64 t; cvta.to.shared.u64 t, %1; cvt.u32.u64 %0, t; }"
        : "=r"(a) : "l"(p));
    return a;
}
__device__ __forceinline__ __half2 uh2(uint32_t u) {
    return *reinterpret_cast<const __half2*>(&u);
}
__device__ __forceinline__ uint32_t h2u(__half2 h) {
    return *reinterpret_cast<const uint32_t*>(&h);
}
__device__ __forceinline__ void ldsm_x4(uint32_t& r0, uint32_t& r1,
                                        uint32_t& r2, uint32_t& r3, uint32_t addr) {
    asm volatile("ldmatrix.sync.aligned.m8n8.x4.shared.b16 {%0,%1,%2,%3}, [%4];"
                 : "=r"(r0), "=r"(r1), "=r"(r2), "=r"(r3) : "r"(addr));
}
__device__ __forceinline__ void mma16816(float* c,
                                         uint32_t a0, uint32_t a1, uint32_t a2, uint32_t a3,
                                         uint32_t b0, uint32_t b1) {
    asm volatile("mma.sync.aligned.m16n8k16.row.col.f32.f16.f16.f32 "
                 "{%0,%1,%2,%3}, {%4,%5,%6,%7}, {%8,%9}, {%0,%1,%2,%3};"
                 : "+f"(c[0]), "+f"(c[1]), "+f"(c[2]), "+f"(c[3])
                 : "r"(a0), "r"(a1), "r"(a2), "r"(a3), "r"(b0), "r"(b1));
}

// ---------------------------------------------------------------------------
// Main: R12 core (6-lane gather + HFMA2 interp, unroll-1 plane loop, HMMA),
// epilogue stores D directly from MMA registers (scalar STG.32 -> no
// alignment hazard on 27-float rows).
// ---------------------------------------------------------------------------
__global__ __launch_bounds__(THREADS, 3)
void tvm_main_kernel(const float* __restrict__ xyz,
                     const float* __restrict__ basisW,
                     float* __restrict__ out,
                     int npts) {
    extern __shared__ char sm[];
    float* sXYZ = reinterpret_cast<float*>(sm + XYZ_OFF);
    const uint32_t sbase = smem_u32(sm);

    const int tid  = threadIdx.x;
    const int base = blockIdx.x * NPTS_BLK;

    // Stage W as fp16 [n=0..31][k=0..143], rows 27-31 zero.
    for (int e = tid; e < WH_BYTES / 16; e += THREADS)
        *reinterpret_cast<uint4*>(sm + WH_OFF + e * 16) = make_uint4(0, 0, 0, 0);
    __syncthreads();
    for (int e = tid; e < NFEAT * KTOT; e += THREADS) {
        const int n = e / KTOT;
        const int k = e - n * KTOT;
        *reinterpret_cast<__half*>(sm + WH_OFF + n * WHROWB + k * 2) =
            __float2half(basisW[e]);
    }
    for (int e = tid; e < NPTS_BLK * 3; e += THREADS) {
        const int p = e / 3;
        const int c = e - p * 3;
        sXYZ[e] = xyz[(size_t)min(base + p, npts - 1) * 3 + c];
    }
    __syncthreads();

    // ---------------- Phase 1: gather + fp16 interp ----------------
    #pragma unroll 1
    for (int it = 0; it < 3; it++) {
        const int s   = tid + it * THREADS;
        const int p   = s / 6;
        const int c16 = s - p * 6;
        const int co  = c16 * 8;

        const float p0 = sXYZ[p * 3 + 0];
        const float p1 = sXYZ[p * 3 + 1];
        const float p2 = sXYZ[p * 3 + 2];

        #pragma unroll 1
        for (int i = 0; i < 3; i++) {
            const float gx = (i == 2) ? p1 : p2;
            const float gy = (i == 0) ? p1 : p0;
            const float gz = (i == 0) ? p0 : ((i == 1) ? p1 : p2);

            const float sc = 0.5f * (float)(RES - 1);
            const float x = (gx + 1.0f) * sc, y = (gy + 1.0f) * sc, z = (gz + 1.0f) * sc;
            const float xf = floorf(x), yf = floorf(y), zf = floorf(z);
            const float wx = x - xf, wy = y - yf, wz = z - zf;
            const int x0 = min(max((int)xf, 0), RES - 1); const int x1 = min(x0 + 1, RES - 1);
            const int y0 = min(max((int)yf, 0), RES - 1); const int y1 = min(y0 + 1, RES - 1);
            const int z0 = min(max((int)zf, 0), RES - 1); const int z1 = min(z0 + 1, RES - 1);

            const __half2 w00h = __float2half2_rn((1.0f - wx) * (1.0f - wy));
            const __half2 w01h = __float2half2_rn(wx * (1.0f - wy));
            const __half2 w10h = __float2half2_rn((1.0f - wx) * wy);
            const __half2 w11h = __float2half2_rn(wx * wy);
            const __half2 lw0h = __float2half2_rn(1.0f - wz);
            const __half2 lw1h = __float2half2_rn(wz);

            const __half* P = g_planesH + (size_t)i * (RES * RES * PCH);
            const __half* L = g_linesH  + (size_t)i * (RES * PCH);
            const uint4 t00 = *(const uint4*)(P + ((size_t)y0 * RES + x0) * PCH + co);
            const uint4 t01 = *(const uint4*)(P + ((size_t)y0 * RES + x1) * PCH + co);
            const uint4 t10 = *(const uint4*)(P + ((size_t)y1 * RES + x0) * PCH + co);
            const uint4 t11 = *(const uint4*)(P + ((size_t)y1 * RES + x1) * PCH + co);
            const uint4 tL0 = *(const uint4*)(L + (size_t)z0 * PCH + co);
            const uint4 tL1 = *(const uint4*)(L + (size_t)z1 * PCH + co);

            const uint32_t* a00 = &t00.x; const uint32_t* a01 = &t01.x;
            const uint32_t* a10 = &t10.x; const uint32_t* a11 = &t11.x;
            const uint32_t* aL0 = &tL0.x; const uint32_t* aL1 = &tL1.x;
            uint32_t fw[4];
            #pragma unroll
            for (int w = 0; w < 4; w++) {
                __half2 pf = __hmul2(w00h, uh2(a00[w]));
                pf = __hfma2(w01h, uh2(a01[w]), pf);
                pf = __hfma2(w10h, uh2(a10[w]), pf);
                pf = __hfma2(w11h, uh2(a11[w]), pf);
                __half2 lf = __hmul2(lw0h, uh2(aL0[w]));
                lf = __hfma2(lw1h, uh2(aL1[w]), lf);
                fw[w] = h2u(__hmul2(pf, lf));
            }
            *reinterpret_cast<uint4*>(sm + F_OFF + (size_t)p * FROWB + (i * NCOMP + co) * 2) =
                make_uint4(fw[0], fw[1], fw[2], fw[3]);
        }
    }
    __syncthreads();

    // ---------------- Phase 2: HMMA matvec + direct scalar store ----------------
    const int wid  = tid >> 5;
    const int lane = tid & 31;
    const int l16  = lane & 15;
    const int g    = lane >> 3;

    const uint32_t a_addr = sbase + F_OFF
        + (uint32_t)(16 * wid + l16) * FROWB + (uint32_t)(lane >> 4) * 16;
    const uint32_t b_addr = sbase + WH_OFF
        + (uint32_t)((g & 2) * 4 + (lane & 7)) * WHROWB + (uint32_t)(g & 1) * 16;

    float c[4][4];
    #pragma unroll
    for (int nt = 0; nt < 4; nt++)
        #pragma unroll
        for (int q = 0; q < 4; q++) c[nt][q] = 0.0f;

    #pragma unroll
    for (int ks = 0; ks < 9; ks++) {
        uint32_t a0, a1, a2, a3;
        ldsm_x4(a0, a1, a2, a3, a_addr + ks * 32);
        #pragma unroll
        for (int ntp = 0; ntp < 2; ntp++) {
            uint32_t b0, b1, b2, b3;
            ldsm_x4(b0, b1, b2, b3, b_addr + (uint32_t)ntp * (16 * WHROWB) + ks * 32);
            mma16816(c[2 * ntp],     a0, a1, a2, a3, b0, b1);
            mma16816(c[2 * ntp + 1], a0, a1, a2, a3, b2, b3);
        }
    }

    // Direct scalar stores: warp owns rows [16*wid, 16*wid+16);
    // lane (gq,t) holds D[gq][nt*8+2t .. +1] and D[gq+8][...] in c[nt].
    {
        const int gq = lane >> 2;
        const int t  = lane & 3;
        const int rA = base + 16 * wid + gq;
        const int rB = rA + 8;
        float* oA = out + (size_t)rA * NFEAT;
        float* oB = out + (size_t)rB * NFEAT;
        const bool vA = (rA < npts);
        const bool vB = (rB < npts);
        #pragma unroll
        for (int nt = 0; nt < 4; nt++) {
            const int j0 = nt * 8 + 2 * t;
            if (j0 < 26) {
                if (vA) { oA[j0] = c[nt][0]; oA[j0 + 1] = c[nt][1]; }
                if (vB) { oB[j0] = c[nt][2]; oB[j0 + 1] = c[nt][3]; }
            } else if (j0 == 26) {
                if (vA) oA[26] = c[nt][0];
                if (vB) oB[26] = c[nt][2];
            }
        }
    }
}

// ---------------------------------------------------------------------------
extern "C" void kernel_launch(void* const* d_in, const int* in_sizes, int n_in,
                              void* d_out, int out_size) {
    const float* xyz    = (const float*)d_in[0];
    const float* planes = (const float*)d_in[1];
    const float* lines  = (const float*)d_in[2];
    const float* basisW = (const float*)d_in[3];
    float* out = (float*)d_out;
    const int npts = in_sizes[0] / 3;

    cudaFuncSetAttribute(tvm_main_kernel,
                         cudaFuncAttributeMaxDynamicSharedMemorySize, SMEM_DYN);

    dim3 tg((RES + 31) / 32, RES, 3);
    transpose_planes_kernel<<<tg, 256>>>(planes);
    transpose_lines_kernel<<<(3 * RES * NCOMP + 255) / 256, 256>>>(lines);
    const int nblk = (npts + NPTS_BLK - 1) / NPTS_BLK;
    tvm_main_kernel<<<nblk, THREADS, SMEM_DYN>>>(xyz, basisW, out, npts);
}